// round 6
// baseline (speedup 1.0000x reference)
#include <cuda_runtime.h>
#include <cstdint>

#define NS 2
#define NB 8
#define NC 32
#define NH 128
#define NW 128
#define NM 32
#define RH 64
#define RW 64

#define TILE_BYTES (RH * RW * 4)   // 16 KB per output tile

// One block = one (n, bm, c) output tile of 64x64 floats (16 KB).
// Phase 1: threads gather the ROI window into SMEM (loads are L2-hits).
// Phase 2: one thread issues a single 16 KB cp.async.bulk SMEM->GMEM store:
//          full-line writes via the TMA/bulk engine, zero L1 store wavefronts.

__global__ __launch_bounds__(256) void roi_patch_kernel(
    const float* __restrict__ fm,
    const int*   __restrict__ boxes,
    float*       __restrict__ out)
{
    __shared__ __align__(128) float tile[RH * RW];

    const int blk = blockIdx.x;
    const int c   = blk & 31;
    const int bm  = (blk >> 5) & 255;
    const int n   = blk >> 13;
    const int b   = bm >> 5;
    const int m   = bm & 31;

    const int4 box = __ldg(reinterpret_cast<const int4*>(boxes)
                           + (n * NB + b) * NM + m);
    const int x1   = box.x;
    const int y1   = box.y;
    const int wbox = box.z - x1;   // valid cols: cc < wbox  (8..64)
    const int hbox = box.w - y1;   // valid rows: r  < hbox  (8..64)

    const int lane16 = threadIdx.x & 15;
    const int r0     = threadIdx.x >> 4;     // 0..15
    const int c0     = lane16 << 2;

    const bool p0 = (c0 + 0) < wbox;
    const bool p1 = (c0 + 1) < wbox;
    const bool p2 = (c0 + 2) < wbox;
    const bool p3 = (c0 + 3) < wbox;

    const float* s0 = fm
        + (((size_t)(n * NB + b) * NC + c) * NH + (y1 + r0)) * NW
        + x1 + c0;

    const float2 z2 = make_float2(0.f, 0.f);
    float2 lo[4], hi[4];

    if ((x1 & 1) == 0) {
        #pragma unroll
        for (int i = 0; i < 4; ++i) {
            const bool rv = (r0 + (i << 4)) < hbox;
            const float* s = s0 + (i << 4) * NW;
            lo[i] = (rv && p0) ? __ldg(reinterpret_cast<const float2*>(s))     : z2;
            hi[i] = (rv && p2) ? __ldg(reinterpret_cast<const float2*>(s + 2)) : z2;
        }
    } else {
        #pragma unroll
        for (int i = 0; i < 4; ++i) {
            const bool rv = (r0 + (i << 4)) < hbox;
            const float* s = s0 + (i << 4) * NW;
            float x = (rv && p0) ? __ldg(s) : 0.f;
            float2 mid = (rv && p1) ? __ldg(reinterpret_cast<const float2*>(s + 1)) : z2;
            float w = (rv && p3) ? __ldg(s + 3) : 0.f;
            lo[i] = make_float2(x, mid.x);
            hi[i] = make_float2(mid.y, w);
        }
    }

    #pragma unroll
    for (int i = 0; i < 4; ++i) {
        float4 v;
        v.x = lo[i].x;
        v.y = p1 ? lo[i].y : 0.f;
        v.z = p2 ? hi[i].x : 0.f;
        v.w = p3 ? hi[i].y : 0.f;
        *reinterpret_cast<float4*>(tile + (((r0 + (i << 4)) << 6) + c0)) = v;
    }

    __syncthreads();

    if (threadIdx.x == 0) {
        // Generic-proxy SMEM writes must be visible to the async proxy.
        asm volatile("fence.proxy.async.shared::cta;" ::: "memory");
        uint32_t saddr;
        asm("{ .reg .u64 t; cvta.to.shared.u64 t, %1; cvt.u32.u64 %0, t; }"
            : "=r"(saddr) : "l"(tile));
        float* gdst = out + ((size_t)blk << 12);
        asm volatile(
            "cp.async.bulk.global.shared::cta.bulk_group [%0], [%1], %2;"
            :: "l"(gdst), "r"(saddr), "n"(TILE_BYTES) : "memory");
        asm volatile("cp.async.bulk.commit_group;" ::: "memory");
        asm volatile("cp.async.bulk.wait_group.read 0;" ::: "memory");
    }
}

extern "C" void kernel_launch(void* const* d_in, const int* in_sizes, int n_in,
                              void* d_out, int out_size)
{
    const float* fm    = (const float*)d_in[0];
    const int*   boxes = (const int*)d_in[1];
    float*       out   = (float*)d_out;

    const int blocks = NS * NB * NM * NC;   // 16384 tiles
    roi_patch_kernel<<<blocks, 256>>>(fm, boxes, out);
}

// round 7
// speedup vs baseline: 1.1568x; 1.1568x over previous
#include <cuda_runtime.h>
#include <cstdint>

#define NS 2
#define NB 8
#define NC 32
#define NH 128
#define NW 128
#define NM 32
#define RH 64
#define RW 64

// One block = one (n, bm, c) output tile of 64x64 floats (16 KB).
// 128 threads; each thread writes 8 float4s at rows r0, r0+8, ..., r0+56.
// ALL 16 load pieces issued before any store -> 2x the in-flight loads per
// warp vs the 256-thread version (attack the L2-hit-latency bound).

__global__ __launch_bounds__(128) void roi_patch_kernel(
    const float* __restrict__ fm,
    const int*   __restrict__ boxes,
    float*       __restrict__ out)
{
    const int blk = blockIdx.x;
    const int c   = blk & 31;
    const int bm  = (blk >> 5) & 255;
    const int n   = blk >> 13;
    const int b   = bm >> 5;
    const int m   = bm & 31;

    const int4 box = __ldg(reinterpret_cast<const int4*>(boxes)
                           + (n * NB + b) * NM + m);
    const int x1   = box.x;
    const int y1   = box.y;
    const int wbox = box.z - x1;   // valid cols: cc < wbox  (8..64)
    const int hbox = box.w - y1;   // valid rows: r  < hbox  (8..64)

    const int lane16 = threadIdx.x & 15;
    const int r0     = threadIdx.x >> 4;     // 0..7
    const int c0     = lane16 << 2;

    const bool p0 = (c0 + 0) < wbox;
    const bool p1 = (c0 + 1) < wbox;
    const bool p2 = (c0 + 2) < wbox;
    const bool p3 = (c0 + 3) < wbox;

    const float* s0 = fm
        + (((size_t)(n * NB + b) * NC + c) * NH + (y1 + r0)) * NW
        + x1 + c0;
    float* dst = out + ((size_t)blk << 12) + (r0 << 6) + c0;

    const float2 z2 = make_float2(0.f, 0.f);
    float2 lo[8], hi[8];

    if ((x1 & 1) == 0) {
        // 8B-aligned window: two LDG.64 per row, all 16 issued before stores.
        #pragma unroll
        for (int i = 0; i < 8; ++i) {
            const bool rv = (r0 + (i << 3)) < hbox;
            const float* s = s0 + (i << 3) * NW;
            lo[i] = (rv && p0) ? __ldg(reinterpret_cast<const float2*>(s))     : z2;
            hi[i] = (rv && p2) ? __ldg(reinterpret_cast<const float2*>(s + 2)) : z2;
        }
    } else {
        // 4B-aligned: LDG.32 + LDG.64 + LDG.32 per row, all issued up front.
        #pragma unroll
        for (int i = 0; i < 8; ++i) {
            const bool rv = (r0 + (i << 3)) < hbox;
            const float* s = s0 + (i << 3) * NW;
            float x    = (rv && p0) ? __ldg(s) : 0.f;
            float2 mid = (rv && p1) ? __ldg(reinterpret_cast<const float2*>(s + 1)) : z2;
            float w    = (rv && p3) ? __ldg(s + 3) : 0.f;
            lo[i] = make_float2(x, mid.x);
            hi[i] = make_float2(mid.y, w);
        }
    }

    #pragma unroll
    for (int i = 0; i < 8; ++i) {
        float4 v;
        v.x = lo[i].x;
        v.y = p1 ? lo[i].y : 0.f;
        v.z = p2 ? hi[i].x : 0.f;
        v.w = p3 ? hi[i].y : 0.f;
        __stcs(reinterpret_cast<float4*>(dst + ((i << 3) << 6)), v);
    }
}

extern "C" void kernel_launch(void* const* d_in, const int* in_sizes, int n_in,
                              void* d_out, int out_size)
{
    const float* fm    = (const float*)d_in[0];
    const int*   boxes = (const int*)d_in[1];
    float*       out   = (float*)d_out;

    const int blocks = NS * NB * NM * NC;   // 16384 tiles
    roi_patch_kernel<<<blocks, 128>>>(fm, boxes, out);
}